// round 4
// baseline (speedup 1.0000x reference)
#include <cuda_runtime.h>
#include <cuda_fp16.h>

#define NN   100000
#define INF  128
#define OUTF 64

// Scratch (allocation-free rule: __device__ globals; guaranteed global space)
__device__ __half g_xws_h[(size_t)NN * OUTF]; // fp16 (X@W)*rsqrt(deg_out)
__device__ float  g_agg[(size_t)NN * OUTF];   // fp32 atomic accumulator
__device__ int    g_deg_out[NN];
__device__ int    g_deg_in[NN];

// ---------------------------------------------------------------------------
// Zero the scratch accumulator and the degree counters
// ---------------------------------------------------------------------------
__global__ void zero_kernel() {
    int stride = gridDim.x * blockDim.x;
    int t = blockIdx.x * blockDim.x + threadIdx.x;
    int n4 = NN * OUTF / 4;
    float4* agg4 = (float4*)g_agg;
    for (int j = t; j < n4; j += stride)
        agg4[j] = make_float4(0.f, 0.f, 0.f, 0.f);
    for (int j = t; j < NN; j += stride) {
        g_deg_out[j] = 0;
        g_deg_in[j]  = 0;
    }
}

// ---------------------------------------------------------------------------
// Degree histogram: 2 int atomics per edge, spread addresses (L2 atomics)
// ---------------------------------------------------------------------------
__global__ void degree_kernel(const int* __restrict__ src,
                              const int* __restrict__ dst, int E) {
    int stride = gridDim.x * blockDim.x;
    for (int e = blockIdx.x * blockDim.x + threadIdx.x; e < E; e += stride) {
        int s = src[e], d = dst[e];
        if ((unsigned)s < NN) atomicAdd(&g_deg_out[s], 1);
        if ((unsigned)d < NN) atomicAdd(&g_deg_in[d],  1);
    }
}

// ---------------------------------------------------------------------------
// xws = fp16( (X @ W) * rsqrt(max(deg_out,1)) )
// Block: 64 rows x 64 cols, 256 threads, thread tile 4x4 (register tiled).
// ---------------------------------------------------------------------------
__global__ __launch_bounds__(256) void gemm_scale_kernel(
    const float* __restrict__ A, const float* __restrict__ W, int n) {
    __shared__ float Ws[INF][OUTF];
    int tid = threadIdx.x;
    for (int i = tid; i < INF * OUTF / 4; i += 256)
        ((float4*)Ws)[i] = ((const float4*)W)[i];
    __syncthreads();

    int ty = tid >> 4;           // 0..15 -> row group
    int tx = tid & 15;           // 0..15 -> col group (4 cols each)
    int row0 = blockIdx.x * 64 + ty * 4;

    float acc[4][4] = {};
    const float4* Ar[4];
    #pragma unroll
    for (int m = 0; m < 4; m++) {
        int r = row0 + m;
        if (r >= n) r = n - 1;   // clamp; result discarded on store
        Ar[m] = (const float4*)(A + (size_t)r * INF);
    }

    for (int k4 = 0; k4 < INF / 4; k4++) {
        float4 a[4];
        #pragma unroll
        for (int m = 0; m < 4; m++) a[m] = __ldg(&Ar[m][k4]);
        #pragma unroll
        for (int kk = 0; kk < 4; kk++) {
            float4 w = *(const float4*)&Ws[k4 * 4 + kk][tx * 4];
            #pragma unroll
            for (int m = 0; m < 4; m++) {
                float av = (kk == 0) ? a[m].x : (kk == 1) ? a[m].y
                         : (kk == 2) ? a[m].z : a[m].w;
                acc[m][0] = fmaf(av, w.x, acc[m][0]);
                acc[m][1] = fmaf(av, w.y, acc[m][1]);
                acc[m][2] = fmaf(av, w.z, acc[m][2]);
                acc[m][3] = fmaf(av, w.w, acc[m][3]);
            }
        }
    }

    #pragma unroll
    for (int m = 0; m < 4; m++) {
        int r = row0 + m;
        if (r < n) {
            int dg = g_deg_out[r];
            float s = rsqrtf((float)(dg > 0 ? dg : 1));
            __half2 h0 = __floats2half2_rn(acc[m][0] * s, acc[m][1] * s);
            __half2 h1 = __floats2half2_rn(acc[m][2] * s, acc[m][3] * s);
            uint2 pk;
            pk.x = *(unsigned*)&h0;
            pk.y = *(unsigned*)&h1;
            *(uint2*)&g_xws_h[(size_t)r * OUTF + tx * 4] = pk;
        }
    }
}

// ---------------------------------------------------------------------------
// Edge scatter: g_agg[dst] += fp32(g_xws_h[src]). 8 lanes per edge, each lane
// gathers one uint4 (16B = 8 halves) and fires two red.global.add.v4.f32
// (fp32 accumulation). Gather traffic halved vs fp32 messages.
// ---------------------------------------------------------------------------
__global__ __launch_bounds__(256) void scatter_kernel(
    const int* __restrict__ src, const int* __restrict__ dst, int E) {
    int gid     = (blockIdx.x * blockDim.x + threadIdx.x) >> 3;
    int lane    = threadIdx.x & 7;
    int ngroups = (gridDim.x * blockDim.x) >> 3;
    for (int e = gid; e < E; e += ngroups) {
        int s = __ldg(&src[e]);
        int d = __ldg(&dst[e]);
        if ((unsigned)s >= NN || (unsigned)d >= NN) continue;
        uint4 h = __ldg((const uint4*)(g_xws_h + (size_t)s * OUTF) + lane);
        float2 f0 = __half22float2(*(__half2*)&h.x);
        float2 f1 = __half22float2(*(__half2*)&h.y);
        float2 f2 = __half22float2(*(__half2*)&h.z);
        float2 f3 = __half22float2(*(__half2*)&h.w);
        float* p = g_agg + (size_t)d * OUTF + lane * 8;
        asm volatile("red.global.add.v4.f32 [%0], {%1, %2, %3, %4};"
                     :: "l"(p), "f"(f0.x), "f"(f0.y), "f"(f1.x), "f"(f1.y)
                     : "memory");
        asm volatile("red.global.add.v4.f32 [%0], {%1, %2, %3, %4};"
                     :: "l"(p + 4), "f"(f2.x), "f"(f2.y), "f"(f3.x), "f"(f3.y)
                     : "memory");
    }
}

// ---------------------------------------------------------------------------
// out = relu(g_agg * rsqrt(max(deg_in,1)) + b)   (plain stores to d_out)
// ---------------------------------------------------------------------------
__global__ void finalize_kernel(float* __restrict__ out,
                                const float* __restrict__ b, int n) {
    int total4 = n * (OUTF / 4);
    int stride = gridDim.x * blockDim.x;
    const float4* agg4 = (const float4*)g_agg;
    for (int j = blockIdx.x * blockDim.x + threadIdx.x; j < total4; j += stride) {
        int node = j >> 4;            // 16 float4 per node
        int c4   = (j & 15) * 4;
        int dg = g_deg_in[node];
        float s = rsqrtf((float)(dg > 0 ? dg : 1));
        float4 v = agg4[j];
        v.x = fmaxf(fmaf(v.x, s, b[c4 + 0]), 0.f);
        v.y = fmaxf(fmaf(v.y, s, b[c4 + 1]), 0.f);
        v.z = fmaxf(fmaf(v.z, s, b[c4 + 2]), 0.f);
        v.w = fmaxf(fmaf(v.w, s, b[c4 + 3]), 0.f);
        ((float4*)out)[j] = v;
    }
}

// ---------------------------------------------------------------------------
// Inputs (metadata order): in_feat f32 [N*128], src i32 [E], dst i32 [E],
//                          W f32 [128*64], b f32 [64]. Output f32 [N*64].
// ---------------------------------------------------------------------------
extern "C" void kernel_launch(void* const* d_in, const int* in_sizes, int n_in,
                              void* d_out, int out_size) {
    const float* in_feat = (const float*)d_in[0];
    const int*   src     = (const int*)d_in[1];
    const int*   dst     = (const int*)d_in[2];
    const float* W       = (const float*)d_in[3];
    const float* b       = (const float*)d_in[4];
    float*       out     = (float*)d_out;

    int n = in_sizes[0] / INF;
    int E = in_sizes[1];

    zero_kernel<<<2048, 256>>>();
    degree_kernel<<<2048, 256>>>(src, dst, E);
    gemm_scale_kernel<<<(n + 63) / 64, 256>>>(in_feat, W, n);
    scatter_kernel<<<8192, 256>>>(src, dst, E);
    finalize_kernel<<<2048, 256>>>(out, b, n);
}

// round 5
// speedup vs baseline: 1.4667x; 1.4667x over previous
#include <cuda_runtime.h>

#define NN   100000
#define INF  128
#define OUTF 64
#define NE_MAX 3200000
#define SCAN_B 1024
#define NBLK  ((NN + SCAN_B - 1) / SCAN_B)   // 98

// Scratch (allocation-free rule: __device__ globals)
__device__ float g_xws[(size_t)NN * OUTF];   // (X@W) * rsqrt(deg_out)
__device__ int   g_deg_out[NN];
__device__ int   g_deg_in[NN];
__device__ int   g_row_off[NN];              // CSR row start (by dst)
__device__ int   g_cursor[NN];               // fill cursor
__device__ int   g_csr_src[NE_MAX];          // src index per CSR slot
__device__ int   g_blocksum[NBLK];
__device__ int   g_blockoff[NBLK];

// ---------------------------------------------------------------------------
__global__ void zero_kernel() {
    int t = blockIdx.x * blockDim.x + threadIdx.x;
    int stride = gridDim.x * blockDim.x;
    for (int j = t; j < NN; j += stride) {
        g_deg_out[j] = 0;
        g_deg_in[j]  = 0;
    }
}

// ---------------------------------------------------------------------------
__global__ void degree_kernel(const int* __restrict__ src,
                              const int* __restrict__ dst, int E) {
    int stride = gridDim.x * blockDim.x;
    for (int e = blockIdx.x * blockDim.x + threadIdx.x; e < E; e += stride) {
        int s = src[e], d = dst[e];
        if ((unsigned)s < NN) atomicAdd(&g_deg_out[s], 1);
        if ((unsigned)d < NN) atomicAdd(&g_deg_in[d],  1);
    }
}

// ---------------------------------------------------------------------------
// Exclusive scan of g_deg_in -> g_row_off  (3 passes)
// ---------------------------------------------------------------------------
__global__ __launch_bounds__(SCAN_B) void scan_local_kernel() {
    __shared__ int sm[SCAN_B];
    int tid = threadIdx.x;
    int gid = blockIdx.x * SCAN_B + tid;
    int val = (gid < NN) ? g_deg_in[gid] : 0;
    sm[tid] = val;
    __syncthreads();
    #pragma unroll
    for (int off = 1; off < SCAN_B; off <<= 1) {
        int t = (tid >= off) ? sm[tid - off] : 0;
        __syncthreads();
        sm[tid] += t;
        __syncthreads();
    }
    if (gid < NN) g_row_off[gid] = sm[tid] - val;   // exclusive (local)
    if (tid == SCAN_B - 1) g_blocksum[blockIdx.x] = sm[tid];
}

__global__ void scan_blocks_kernel() {
    if (threadIdx.x == 0 && blockIdx.x == 0) {
        int run = 0;
        for (int i = 0; i < NBLK; i++) {
            g_blockoff[i] = run;
            run += g_blocksum[i];
        }
    }
}

__global__ __launch_bounds__(SCAN_B) void scan_add_kernel() {
    int gid = blockIdx.x * SCAN_B + threadIdx.x;
    if (gid < NN) {
        int v = g_row_off[gid] + g_blockoff[blockIdx.x];
        g_row_off[gid] = v;
        g_cursor[gid]  = v;
    }
}

// ---------------------------------------------------------------------------
// CSR fill: one int atomic + one 4B write per edge
// ---------------------------------------------------------------------------
__global__ void csr_fill_kernel(const int* __restrict__ src,
                                const int* __restrict__ dst, int E) {
    int stride = gridDim.x * blockDim.x;
    for (int e = blockIdx.x * blockDim.x + threadIdx.x; e < E; e += stride) {
        int s = src[e], d = dst[e];
        if ((unsigned)s >= NN || (unsigned)d >= NN) continue;
        int pos = atomicAdd(&g_cursor[d], 1);
        g_csr_src[pos] = s;
    }
}

// ---------------------------------------------------------------------------
// xws = (X @ W) * rsqrt(max(deg_out,1))   (fp32, register tiled 4x4)
// ---------------------------------------------------------------------------
__global__ __launch_bounds__(256) void gemm_scale_kernel(
    const float* __restrict__ A, const float* __restrict__ W, int n) {
    __shared__ float Ws[INF][OUTF];
    int tid = threadIdx.x;
    for (int i = tid; i < INF * OUTF / 4; i += 256)
        ((float4*)Ws)[i] = ((const float4*)W)[i];
    __syncthreads();

    int ty = tid >> 4;
    int tx = tid & 15;
    int row0 = blockIdx.x * 64 + ty * 4;

    float acc[4][4] = {};
    const float4* Ar[4];
    #pragma unroll
    for (int m = 0; m < 4; m++) {
        int r = row0 + m;
        if (r >= n) r = n - 1;
        Ar[m] = (const float4*)(A + (size_t)r * INF);
    }

    for (int k4 = 0; k4 < INF / 4; k4++) {
        float4 a[4];
        #pragma unroll
        for (int m = 0; m < 4; m++) a[m] = __ldg(&Ar[m][k4]);
        #pragma unroll
        for (int kk = 0; kk < 4; kk++) {
            float4 w = *(const float4*)&Ws[k4 * 4 + kk][tx * 4];
            #pragma unroll
            for (int m = 0; m < 4; m++) {
                float av = (kk == 0) ? a[m].x : (kk == 1) ? a[m].y
                         : (kk == 2) ? a[m].z : a[m].w;
                acc[m][0] = fmaf(av, w.x, acc[m][0]);
                acc[m][1] = fmaf(av, w.y, acc[m][1]);
                acc[m][2] = fmaf(av, w.z, acc[m][2]);
                acc[m][3] = fmaf(av, w.w, acc[m][3]);
            }
        }
    }

    #pragma unroll
    for (int m = 0; m < 4; m++) {
        int r = row0 + m;
        if (r < n) {
            int dg = g_deg_out[r];
            float s = rsqrtf((float)(dg > 0 ? dg : 1));
            float4 v = make_float4(acc[m][0] * s, acc[m][1] * s,
                                   acc[m][2] * s, acc[m][3] * s);
            *(float4*)&g_xws[(size_t)r * OUTF + tx * 4] = v;
        }
    }
}

// ---------------------------------------------------------------------------
// Aggregate: one warp per dst node. Lane c owns output floats [2c, 2c+1].
// Per edge, all 32 lanes read the 256B row of g_xws[src] (coalesced, 2 L2
// lines) and accumulate in registers. No atomics. Fused finalize.
// ---------------------------------------------------------------------------
__global__ __launch_bounds__(256) void aggregate_kernel(
    float* __restrict__ out, const float* __restrict__ b, int n) {
    int warp = (blockIdx.x * blockDim.x + threadIdx.x) >> 5;
    if (warp >= n) return;
    int lane = threadIdx.x & 31;

    int start = g_row_off[warp];
    int deg   = g_deg_in[warp];

    float accx = 0.f, accy = 0.f;
    const float2* base = (const float2*)g_xws;

    for (int e0 = 0; e0 < deg; e0 += 32) {
        int me  = e0 + lane;
        int s   = (me < deg) ? __ldg(&g_csr_src[start + me]) : 0;
        int cnt = deg - e0; if (cnt > 32) cnt = 32;
        int j = 0;
        #pragma unroll 1
        for (; j + 4 <= cnt; j += 4) {
            int s0 = __shfl_sync(0xffffffffu, s, j + 0);
            int s1 = __shfl_sync(0xffffffffu, s, j + 1);
            int s2 = __shfl_sync(0xffffffffu, s, j + 2);
            int s3 = __shfl_sync(0xffffffffu, s, j + 3);
            float2 v0 = __ldg(base + (size_t)s0 * 32 + lane);
            float2 v1 = __ldg(base + (size_t)s1 * 32 + lane);
            float2 v2 = __ldg(base + (size_t)s2 * 32 + lane);
            float2 v3 = __ldg(base + (size_t)s3 * 32 + lane);
            accx += v0.x + v1.x + v2.x + v3.x;
            accy += v0.y + v1.y + v2.y + v3.y;
        }
        for (; j < cnt; j++) {
            int sj = __shfl_sync(0xffffffffu, s, j);
            float2 v = __ldg(base + (size_t)sj * 32 + lane);
            accx += v.x;
            accy += v.y;
        }
    }

    float sc = rsqrtf((float)(deg > 0 ? deg : 1));
    float2 bb = __ldg((const float2*)b + lane);
    float2 r;
    r.x = fmaxf(fmaf(accx, sc, bb.x), 0.f);
    r.y = fmaxf(fmaf(accy, sc, bb.y), 0.f);
    ((float2*)out)[(size_t)warp * 32 + lane] = r;
}

// ---------------------------------------------------------------------------
extern "C" void kernel_launch(void* const* d_in, const int* in_sizes, int n_in,
                              void* d_out, int out_size) {
    const float* in_feat = (const float*)d_in[0];
    const int*   src     = (const int*)d_in[1];
    const int*   dst     = (const int*)d_in[2];
    const float* W       = (const float*)d_in[3];
    const float* b       = (const float*)d_in[4];
    float*       out     = (float*)d_out;

    int n = in_sizes[0] / INF;
    int E = in_sizes[1];

    zero_kernel<<<512, 256>>>();
    degree_kernel<<<2048, 256>>>(src, dst, E);
    scan_local_kernel<<<NBLK, SCAN_B>>>();
    scan_blocks_kernel<<<1, 32>>>();
    scan_add_kernel<<<NBLK, SCAN_B>>>();
    csr_fill_kernel<<<2048, 256>>>(src, dst, E);
    gemm_scale_kernel<<<(n + 63) / 64, 256>>>(in_feat, W, n);
    aggregate_kernel<<<(n * 32 + 255) / 256, 256>>>(out, b, n);
}

// round 6
// speedup vs baseline: 1.6039x; 1.0935x over previous
#include <cuda_runtime.h>
#include <cuda_fp16.h>

#define NN   100000
#define INF  128
#define OUTF 64
#define NE_MAX 3200000
#define SCAN_B 1024
#define NBLK  ((NN + SCAN_B - 1) / SCAN_B)   // 98

// Scratch (allocation-free rule: __device__ globals)
__device__ __half g_xws_h[(size_t)NN * OUTF]; // fp16 (X@W)*rsqrt(deg_out)
__device__ int    g_deg_out[NN];
__device__ int    g_deg_in[NN];
__device__ int    g_row_off[NN];              // CSR row start (by dst)
__device__ int    g_cursor[NN];               // fill cursor
__device__ int    g_csr_src[NE_MAX];          // src index per CSR slot
__device__ int    g_blocksum[NBLK];
__device__ int    g_blockoff[NBLK];

// ---------------------------------------------------------------------------
__global__ void zero_kernel() {
    int t = blockIdx.x * blockDim.x + threadIdx.x;
    int stride = gridDim.x * blockDim.x;
    for (int j = t; j < NN; j += stride) {
        g_deg_out[j] = 0;
        g_deg_in[j]  = 0;
    }
}

// ---------------------------------------------------------------------------
__global__ void degree_kernel(const int* __restrict__ src,
                              const int* __restrict__ dst, int E) {
    int stride = gridDim.x * blockDim.x;
    for (int e = blockIdx.x * blockDim.x + threadIdx.x; e < E; e += stride) {
        int s = src[e], d = dst[e];
        if ((unsigned)s < NN) atomicAdd(&g_deg_out[s], 1);
        if ((unsigned)d < NN) atomicAdd(&g_deg_in[d],  1);
    }
}

// ---------------------------------------------------------------------------
// Exclusive scan of g_deg_in -> g_row_off  (3 passes)
// ---------------------------------------------------------------------------
__global__ __launch_bounds__(SCAN_B) void scan_local_kernel() {
    __shared__ int sm[SCAN_B];
    int tid = threadIdx.x;
    int gid = blockIdx.x * SCAN_B + tid;
    int val = (gid < NN) ? g_deg_in[gid] : 0;
    sm[tid] = val;
    __syncthreads();
    #pragma unroll
    for (int off = 1; off < SCAN_B; off <<= 1) {
        int t = (tid >= off) ? sm[tid - off] : 0;
        __syncthreads();
        sm[tid] += t;
        __syncthreads();
    }
    if (gid < NN) g_row_off[gid] = sm[tid] - val;   // exclusive (local)
    if (tid == SCAN_B - 1) g_blocksum[blockIdx.x] = sm[tid];
}

// Parallel Hillis-Steele over the 98 block sums (was: 1 thread x 98 L2 RTTs)
__global__ __launch_bounds__(128) void scan_blocks_kernel() {
    __shared__ int sm[128];
    int t = threadIdx.x;
    int val = (t < NBLK) ? g_blocksum[t] : 0;
    sm[t] = val;
    __syncthreads();
    #pragma unroll
    for (int off = 1; off < 128; off <<= 1) {
        int u = (t >= off) ? sm[t - off] : 0;
        __syncthreads();
        sm[t] += u;
        __syncthreads();
    }
    if (t < NBLK) g_blockoff[t] = sm[t] - val;      // exclusive
}

__global__ __launch_bounds__(SCAN_B) void scan_add_kernel() {
    int gid = blockIdx.x * SCAN_B + threadIdx.x;
    if (gid < NN) {
        int v = g_row_off[gid] + g_blockoff[blockIdx.x];
        g_row_off[gid] = v;
        g_cursor[gid]  = v;
    }
}

// ---------------------------------------------------------------------------
// CSR fill: one int atomic + one 4B write per edge
// ---------------------------------------------------------------------------
__global__ void csr_fill_kernel(const int* __restrict__ src,
                                const int* __restrict__ dst, int E) {
    int stride = gridDim.x * blockDim.x;
    for (int e = blockIdx.x * blockDim.x + threadIdx.x; e < E; e += stride) {
        int s = src[e], d = dst[e];
        if ((unsigned)s >= NN || (unsigned)d >= NN) continue;
        int pos = atomicAdd(&g_cursor[d], 1);
        g_csr_src[pos] = s;
    }
}

// ---------------------------------------------------------------------------
// xws = fp16( (X @ W) * rsqrt(max(deg_out,1)) )
// Register tiled 4x4 with packed fma.rn.f32x2 (FFMA2): column pairs of W come
// straight out of the LDS.128 as register pairs; only {av,av} needs packing.
// ---------------------------------------------------------------------------
__global__ __launch_bounds__(256) void gemm_scale_kernel(
    const float* __restrict__ A, const float* __restrict__ W, int n) {
    __shared__ float Ws[INF][OUTF];
    int tid = threadIdx.x;
    for (int i = tid; i < INF * OUTF / 4; i += 256)
        ((float4*)Ws)[i] = ((const float4*)W)[i];
    __syncthreads();

    int ty = tid >> 4;
    int tx = tid & 15;
    int row0 = blockIdx.x * 64 + ty * 4;

    unsigned long long acc[4][2] = {};   // packed f32x2 pairs; 0ull == {0,0}
    const float4* Ar[4];
    #pragma unroll
    for (int m = 0; m < 4; m++) {
        int r = row0 + m;
        if (r >= n) r = n - 1;
        Ar[m] = (const float4*)(A + (size_t)r * INF);
    }

    for (int k4 = 0; k4 < INF / 4; k4++) {
        float4 a[4];
        #pragma unroll
        for (int m = 0; m < 4; m++) a[m] = __ldg(&Ar[m][k4]);
        #pragma unroll
        for (int kk = 0; kk < 4; kk++) {
            float4 w = *(const float4*)&Ws[k4 * 4 + kk][tx * 4];
            unsigned long long b01, b23;
            asm("mov.b64 %0, {%1, %2};" : "=l"(b01) : "f"(w.x), "f"(w.y));
            asm("mov.b64 %0, {%1, %2};" : "=l"(b23) : "f"(w.z), "f"(w.w));
            #pragma unroll
            for (int m = 0; m < 4; m++) {
                float av = (kk == 0) ? a[m].x : (kk == 1) ? a[m].y
                         : (kk == 2) ? a[m].z : a[m].w;
                unsigned long long ap;
                asm("mov.b64 %0, {%1, %1};" : "=l"(ap) : "f"(av));
                asm("fma.rn.f32x2 %0, %1, %2, %0;" : "+l"(acc[m][0])
                    : "l"(ap), "l"(b01));
                asm("fma.rn.f32x2 %0, %1, %2, %0;" : "+l"(acc[m][1])
                    : "l"(ap), "l"(b23));
            }
        }
    }

    #pragma unroll
    for (int m = 0; m < 4; m++) {
        int r = row0 + m;
        if (r < n) {
            int dg = g_deg_out[r];
            float s = rsqrtf((float)(dg > 0 ? dg : 1));
            float c0, c1, c2, c3;
            asm("mov.b64 {%0, %1}, %2;" : "=f"(c0), "=f"(c1) : "l"(acc[m][0]));
            asm("mov.b64 {%0, %1}, %2;" : "=f"(c2), "=f"(c3) : "l"(acc[m][1]));
            __half2 h0 = __floats2half2_rn(c0 * s, c1 * s);
            __half2 h1 = __floats2half2_rn(c2 * s, c3 * s);
            uint2 pk;
            pk.x = *(unsigned*)&h0;
            pk.y = *(unsigned*)&h1;
            *(uint2*)&g_xws_h[(size_t)r * OUTF + tx * 4] = pk;
        }
    }
}

// ---------------------------------------------------------------------------
// Aggregate: one warp per dst node. Lane c owns output cols [2c, 2c+1].
// Per edge, the warp reads the 128B fp16 row of g_xws_h[src] (one L2 line),
// accumulates in fp32 registers. No atomics. Fused rsqrt(deg_in)+bias+relu.
// ---------------------------------------------------------------------------
__global__ __launch_bounds__(256) void aggregate_kernel(
    float* __restrict__ out, const float* __restrict__ b, int n) {
    int warp = (blockIdx.x * blockDim.x + threadIdx.x) >> 5;
    if (warp >= n) return;
    int lane = threadIdx.x & 31;

    int start = g_row_off[warp];
    int deg   = g_deg_in[warp];

    float accx = 0.f, accy = 0.f;
    const __half2* base = (const __half2*)g_xws_h;

    for (int e0 = 0; e0 < deg; e0 += 32) {
        int me  = e0 + lane;
        int s   = (me < deg) ? __ldg(&g_csr_src[start + me]) : 0;
        int cnt = deg - e0; if (cnt > 32) cnt = 32;
        int j = 0;
        #pragma unroll 1
        for (; j + 4 <= cnt; j += 4) {
            int s0 = __shfl_sync(0xffffffffu, s, j + 0);
            int s1 = __shfl_sync(0xffffffffu, s, j + 1);
            int s2 = __shfl_sync(0xffffffffu, s, j + 2);
            int s3 = __shfl_sync(0xffffffffu, s, j + 3);
            float2 v0 = __half22float2(__ldg(base + (size_t)s0 * 32 + lane));
            float2 v1 = __half22float2(__ldg(base + (size_t)s1 * 32 + lane));
            float2 v2 = __half22float2(__ldg(base + (size_t)s2 * 32 + lane));
            float2 v3 = __half22float2(__ldg(base + (size_t)s3 * 32 + lane));
            accx += (v0.x + v1.x) + (v2.x + v3.x);
            accy += (v0.y + v1.y) + (v2.y + v3.y);
        }
        for (; j < cnt; j++) {
            int sj = __shfl_sync(0xffffffffu, s, j);
            float2 v = __half22float2(__ldg(base + (size_t)sj * 32 + lane));
            accx += v.x;
            accy += v.y;
        }
    }

    float sc = rsqrtf((float)(deg > 0 ? deg : 1));
    float2 bb = __ldg((const float2*)b + lane);
    float2 r;
    r.x = fmaxf(fmaf(accx, sc, bb.x), 0.f);
    r.y = fmaxf(fmaf(accy, sc, bb.y), 0.f);
    ((float2*)out)[(size_t)warp * 32 + lane] = r;
}

// ---------------------------------------------------------------------------
extern "C" void kernel_launch(void* const* d_in, const int* in_sizes, int n_in,
                              void* d_out, int out_size) {
    const float* in_feat = (const float*)d_in[0];
    const int*   src     = (const int*)d_in[1];
    const int*   dst     = (const int*)d_in[2];
    const float* W       = (const float*)d_in[3];
    const float* b       = (const float*)d_in[4];
    float*       out     = (float*)d_out;

    int n = in_sizes[0] / INF;
    int E = in_sizes[1];

    zero_kernel<<<512, 256>>>();
    degree_kernel<<<2048, 256>>>(src, dst, E);
    scan_local_kernel<<<NBLK, SCAN_B>>>();
    scan_blocks_kernel<<<1, 128>>>();
    scan_add_kernel<<<NBLK, SCAN_B>>>();
    csr_fill_kernel<<<2048, 256>>>(src, dst, E);
    gemm_scale_kernel<<<(n + 63) / 64, 256>>>(in_feat, W, n);
    aggregate_kernel<<<(n * 32 + 255) / 256, 256>>>(out, b, n);
}

// round 7
// speedup vs baseline: 1.8323x; 1.1424x over previous
#include <cuda_runtime.h>
#include <cuda_fp16.h>

#define NN   100000
#define INF  128
#define OUTF 64
#define NE_MAX 3200000
#define SCAN_B 1024
#define NBLK  ((NN + SCAN_B - 1) / SCAN_B)   // 98
#define WPAD  72                             // W smem pitch: conflict-free B frags

// Scratch (allocation-free rule: __device__ globals)
__device__ __half g_xws_h[(size_t)NN * OUTF]; // fp16 (X@W)*rsqrt(deg_out)
__device__ int    g_deg_out[NN];
__device__ int    g_deg_in[NN];
__device__ int    g_row_off[NN];              // CSR row start (by dst)
__device__ int    g_cursor[NN];               // fill cursor
__device__ int    g_csr_src[NE_MAX];          // src index per CSR slot
__device__ int    g_blocksum[NBLK];
__device__ int    g_blockoff[NBLK];

// ---------------------------------------------------------------------------
__global__ void zero_kernel() {
    int t = blockIdx.x * blockDim.x + threadIdx.x;
    int stride = gridDim.x * blockDim.x;
    for (int j = t; j < NN; j += stride) {
        g_deg_out[j] = 0;
        g_deg_in[j]  = 0;
    }
}

// ---------------------------------------------------------------------------
__global__ void degree_kernel(const int* __restrict__ src,
                              const int* __restrict__ dst, int E) {
    int stride = gridDim.x * blockDim.x;
    for (int e = blockIdx.x * blockDim.x + threadIdx.x; e < E; e += stride) {
        int s = src[e], d = dst[e];
        if ((unsigned)s < NN) atomicAdd(&g_deg_out[s], 1);
        if ((unsigned)d < NN) atomicAdd(&g_deg_in[d],  1);
    }
}

// ---------------------------------------------------------------------------
// Exclusive scan of g_deg_in -> g_row_off  (3 passes)
// ---------------------------------------------------------------------------
__global__ __launch_bounds__(SCAN_B) void scan_local_kernel() {
    __shared__ int sm[SCAN_B];
    int tid = threadIdx.x;
    int gid = blockIdx.x * SCAN_B + tid;
    int val = (gid < NN) ? g_deg_in[gid] : 0;
    sm[tid] = val;
    __syncthreads();
    #pragma unroll
    for (int off = 1; off < SCAN_B; off <<= 1) {
        int t = (tid >= off) ? sm[tid - off] : 0;
        __syncthreads();
        sm[tid] += t;
        __syncthreads();
    }
    if (gid < NN) g_row_off[gid] = sm[tid] - val;   // exclusive (local)
    if (tid == SCAN_B - 1) g_blocksum[blockIdx.x] = sm[tid];
}

__global__ __launch_bounds__(128) void scan_blocks_kernel() {
    __shared__ int sm[128];
    int t = threadIdx.x;
    int val = (t < NBLK) ? g_blocksum[t] : 0;
    sm[t] = val;
    __syncthreads();
    #pragma unroll
    for (int off = 1; off < 128; off <<= 1) {
        int u = (t >= off) ? sm[t - off] : 0;
        __syncthreads();
        sm[t] += u;
        __syncthreads();
    }
    if (t < NBLK) g_blockoff[t] = sm[t] - val;      // exclusive
}

__global__ __launch_bounds__(SCAN_B) void scan_add_kernel() {
    int gid = blockIdx.x * SCAN_B + threadIdx.x;
    if (gid < NN) {
        int v = g_row_off[gid] + g_blockoff[blockIdx.x];
        g_row_off[gid] = v;
        g_cursor[gid]  = v;
    }
}

// ---------------------------------------------------------------------------
// CSR fill: one int atomic + one 4B write per edge
// ---------------------------------------------------------------------------
__global__ void csr_fill_kernel(const int* __restrict__ src,
                                const int* __restrict__ dst, int E) {
    int stride = gridDim.x * blockDim.x;
    for (int e = blockIdx.x * blockDim.x + threadIdx.x; e < E; e += stride) {
        int s = src[e], d = dst[e];
        if ((unsigned)s >= NN || (unsigned)d >= NN) continue;
        int pos = atomicAdd(&g_cursor[d], 1);
        g_csr_src[pos] = s;
    }
}

// ---------------------------------------------------------------------------
// Tensor-core GEMM: xws = fp16( (A @ W) * rsqrt(max(deg_out,1)) )
// mma.sync.m16n8k8 tf32. One warp = 16 rows x 64 cols (16 k-steps x 8 n-tiles).
// W staged in smem as tf32 with pitch 72 -> B-fragment LDS bank-conflict-free.
// ---------------------------------------------------------------------------
__global__ __launch_bounds__(256) void gemm_mma_kernel(
    const float* __restrict__ A, const float* __restrict__ W, int n) {
    __shared__ unsigned Ws[INF][WPAD];
    int tid = threadIdx.x;
    for (int i = tid; i < INF * OUTF; i += 256) {
        int k = i >> 6, c = i & 63;
        unsigned t;
        asm("cvt.rna.tf32.f32 %0, %1;" : "=r"(t) : "f"(W[i]));
        Ws[k][c] = t;
    }
    __syncthreads();

    int warp = tid >> 5;
    int lane = tid & 31;
    int g  = lane >> 2;      // 0..7
    int tg = lane & 3;       // 0..3
    int row0 = (blockIdx.x * 8 + warp) * 16;

    int r_lo = row0 + g;
    int r_hi = row0 + g + 8;
    int r_lo_c = r_lo < n ? r_lo : n - 1;
    int r_hi_c = r_hi < n ? r_hi : n - 1;
    const float* Alo = A + (size_t)r_lo_c * INF;
    const float* Ahi = A + (size_t)r_hi_c * INF;

    float acc[8][4];
    #pragma unroll
    for (int nt = 0; nt < 8; nt++)
        #pragma unroll
        for (int c = 0; c < 4; c++) acc[nt][c] = 0.f;

    #pragma unroll
    for (int kk = 0; kk < 16; kk++) {
        int k0 = kk * 8;
        float a0f = __ldg(&Alo[k0 + tg]);
        float a1f = __ldg(&Ahi[k0 + tg]);
        float a2f = __ldg(&Alo[k0 + tg + 4]);
        float a3f = __ldg(&Ahi[k0 + tg + 4]);
        unsigned a0, a1, a2, a3;
        asm("cvt.rna.tf32.f32 %0, %1;" : "=r"(a0) : "f"(a0f));
        asm("cvt.rna.tf32.f32 %0, %1;" : "=r"(a1) : "f"(a1f));
        asm("cvt.rna.tf32.f32 %0, %1;" : "=r"(a2) : "f"(a2f));
        asm("cvt.rna.tf32.f32 %0, %1;" : "=r"(a3) : "f"(a3f));
        #pragma unroll
        for (int nt = 0; nt < 8; nt++) {
            unsigned b0 = Ws[k0 + tg][nt * 8 + g];
            unsigned b1 = Ws[k0 + tg + 4][nt * 8 + g];
            asm("mma.sync.aligned.m16n8k8.row.col.f32.tf32.tf32.f32 "
                "{%0,%1,%2,%3}, {%4,%5,%6,%7}, {%8,%9}, {%0,%1,%2,%3};"
                : "+f"(acc[nt][0]), "+f"(acc[nt][1]),
                  "+f"(acc[nt][2]), "+f"(acc[nt][3])
                : "r"(a0), "r"(a1), "r"(a2), "r"(a3), "r"(b0), "r"(b1));
        }
    }

    float s_lo = 1.f, s_hi = 1.f;
    if (r_lo < n) {
        int dg = g_deg_out[r_lo];
        s_lo = rsqrtf((float)(dg > 0 ? dg : 1));
    }
    if (r_hi < n) {
        int dg = g_deg_out[r_hi];
        s_hi = rsqrtf((float)(dg > 0 ? dg : 1));
    }
    #pragma unroll
    for (int nt = 0; nt < 8; nt++) {
        int col = nt * 8 + 2 * tg;
        if (r_lo < n) {
            __half2 h = __floats2half2_rn(acc[nt][0] * s_lo, acc[nt][1] * s_lo);
            *(__half2*)&g_xws_h[(size_t)r_lo * OUTF + col] = h;
        }
        if (r_hi < n) {
            __half2 h = __floats2half2_rn(acc[nt][2] * s_hi, acc[nt][3] * s_hi);
            *(__half2*)&g_xws_h[(size_t)r_hi * OUTF + col] = h;
        }
    }
}

// ---------------------------------------------------------------------------
// Aggregate: one warp per dst node. Lane c owns output cols [2c, 2c+1].
// Per edge, the warp reads the 128B fp16 row of g_xws_h[src] (one L2 line),
// accumulates in fp32 registers. No atomics. Fused rsqrt(deg_in)+bias+relu.
// ---------------------------------------------------------------------------
__global__ __launch_bounds__(256) void aggregate_kernel(
    float* __restrict__ out, const float* __restrict__ b, int n) {
    int warp = (blockIdx.x * blockDim.x + threadIdx.x) >> 5;
    if (warp >= n) return;
    int lane = threadIdx.x & 31;

    int start = g_row_off[warp];
    int deg   = g_deg_in[warp];

    float accx = 0.f, accy = 0.f;
    const __half2* base = (const __half2*)g_xws_h;

    for (int e0 = 0; e0 < deg; e0 += 32) {
        int me  = e0 + lane;
        int s   = (me < deg) ? __ldg(&g_csr_src[start + me]) : 0;
        int cnt = deg - e0; if (cnt > 32) cnt = 32;
        int j = 0;
        #pragma unroll 1
        for (; j + 4 <= cnt; j += 4) {
            int s0 = __shfl_sync(0xffffffffu, s, j + 0);
            int s1 = __shfl_sync(0xffffffffu, s, j + 1);
            int s2 = __shfl_sync(0xffffffffu, s, j + 2);
            int s3 = __shfl_sync(0xffffffffu, s, j + 3);
            float2 v0 = __half22float2(__ldg(base + (size_t)s0 * 32 + lane));
            float2 v1 = __half22float2(__ldg(base + (size_t)s1 * 32 + lane));
            float2 v2 = __half22float2(__ldg(base + (size_t)s2 * 32 + lane));
            float2 v3 = __half22float2(__ldg(base + (size_t)s3 * 32 + lane));
            accx += (v0.x + v1.x) + (v2.x + v3.x);
            accy += (v0.y + v1.y) + (v2.y + v3.y);
        }
        for (; j < cnt; j++) {
            int sj = __shfl_sync(0xffffffffu, s, j);
            float2 v = __half22float2(__ldg(base + (size_t)sj * 32 + lane));
            accx += v.x;
            accy += v.y;
        }
    }

    float sc = rsqrtf((float)(deg > 0 ? deg : 1));
    float2 bb = __ldg((const float2*)b + lane);
    float2 r;
    r.x = fmaxf(fmaf(accx, sc, bb.x), 0.f);
    r.y = fmaxf(fmaf(accy, sc, bb.y), 0.f);
    ((float2*)out)[(size_t)warp * 32 + lane] = r;
}

// ---------------------------------------------------------------------------
extern "C" void kernel_launch(void* const* d_in, const int* in_sizes, int n_in,
                              void* d_out, int out_size) {
    const float* in_feat = (const float*)d_in[0];
    const int*   src     = (const int*)d_in[1];
    const int*   dst     = (const int*)d_in[2];
    const float* W       = (const float*)d_in[3];
    const float* b       = (const float*)d_in[4];
    float*       out     = (float*)d_out;

    int n = in_sizes[0] / INF;
    int E = in_sizes[1];

    zero_kernel<<<512, 256>>>();
    degree_kernel<<<2048, 256>>>(src, dst, E);
    scan_local_kernel<<<NBLK, SCAN_B>>>();
    scan_blocks_kernel<<<1, 128>>>();
    scan_add_kernel<<<NBLK, SCAN_B>>>();
    csr_fill_kernel<<<2048, 256>>>(src, dst, E);
    gemm_mma_kernel<<<(n + 127) / 128, 256>>>(in_feat, W, n);
    aggregate_kernel<<<(n * 32 + 255) / 256, 256>>>(out, b, n);
}